// round 12
// baseline (speedup 1.0000x reference)
#include <cuda_runtime.h>
#include <cuda_bf16.h>
#include <math.h>

// Problem constants (from reference): B=8, N=256, MAX_DIM=2, D=4, EPS=1e-8
#define NP 256
#define NBLK 2     // 2 blocks x 8 warps = 16 warps = 16 cells
#define NCELL 16   // B * MAX_DIM partial sums

__device__ float g_partial[NCELL];
__device__ unsigned int g_count;   // static-init 0; atomicInc wraps back to 0

// Warp-register bitonic sort of TWO independent 256-float sequences at once
// (2-way ILP hides SHFL latency). 8 elements per lane, e = (lane<<3)|r.
// Cross-lane strides (j>=8) use shfl_xor + min/max; in-register strides use
// branch-free fmin/fmax compare-exchange chains.
__device__ __forceinline__ void warp_bitonic_256x2(float a[8], float b[8], int lane) {
    #pragma unroll
    for (int k = 2; k <= 256; k <<= 1) {
        #pragma unroll
        for (int j = k >> 1; j > 0; j >>= 1) {
            if (j >= 8) {
                const int lmask = j >> 3;
                const bool upper = (lane & lmask) != 0;
                #pragma unroll
                for (int r = 0; r < 8; r++) {
                    // j>=8 -> k>=16, so asc depends only on lane bits
                    bool asc = ((((lane << 3) | r) & k) == 0);
                    bool takeMax = (upper == asc);
                    float oa = __shfl_xor_sync(0xffffffffu, a[r], lmask);
                    float ob = __shfl_xor_sync(0xffffffffu, b[r], lmask);
                    a[r] = takeMax ? fmaxf(a[r], oa) : fminf(a[r], oa);
                    b[r] = takeMax ? fmaxf(b[r], ob) : fminf(b[r], ob);
                }
            } else {
                #pragma unroll
                for (int r = 0; r < 8; r++) {
                    int p = r ^ j;
                    if (p > r) {
                        bool asc = ((((lane << 3) | r) & k) == 0);
                        float alo = fminf(a[r], a[p]);
                        float ahi = fmaxf(a[r], a[p]);
                        a[r] = asc ? alo : ahi;
                        a[p] = asc ? ahi : alo;
                        float blo = fminf(b[r], b[p]);
                        float bhi = fmaxf(b[r], b[p]);
                        b[r] = asc ? blo : bhi;
                        b[p] = asc ? bhi : blo;
                    }
                }
            }
        }
    }
}

// 2 blocks x 256 threads (8 warps = 2 per SMSP, so ILP-2 shfl chains from
// co-resident warps interleave). Warp w of block g owns cell 8g+w: it loads
// and projects BOTH arrays of that (batch, dim), sorts them together in
// registers (no smem, no barriers), and takes the L1 diff in-register.
// Sorted matching == optimal assignment for 1D L1 cost; the 2B LAPs come in
// transpose pairs with equal totals -> factor 2. Last finishing block sums
// the 16 per-cell partials in fixed index order (deterministic) into out[0].
__global__ __launch_bounds__(256)
void hungarian_warpcell_kernel(const float* __restrict__ set1,
                               const float* __restrict__ set2,
                               float* __restrict__ out) {
    __shared__ float wsum[8];

    const int tid  = threadIdx.x;
    const int w    = tid >> 5;                 // warp 0..7
    const int lane = tid & 31;
    const int cell = blockIdx.x * 8 + w;       // 0..15
    const int b    = cell >> 1;
    const int dim  = cell & 1;
    const float fdim = (float)dim;

    float va[8], vb[8];
    const float4* s1 = (const float4*)set1 + (size_t)b * NP;
    const float4* s2 = (const float4*)set2 + (size_t)b * NP;

    #pragma unroll
    for (int r = 0; r < 8; r++) {
        int e = (lane << 3) | r;
        float4 p = s1[e];
        bool m = (p.z == fdim);
        va[r] = (m ? p.x : 0.0f) + sqrtf((m ? p.y : 0.0f) + 1e-8f) * 0.5f;

        float4 q = s2[e];
        // jnp.argmax over (c2, c3): first max wins -> label 1 iff c3 > c2
        bool m2 = (((q.w > q.z) ? 1 : 0) == dim);
        vb[r] = (m2 ? q.x : 0.0f) + sqrtf((m2 ? q.y : 0.0f) + 1e-8f) * 0.5f;
    }

    warp_bitonic_256x2(va, vb, lane);

    // in-register L1 diff + warp reduce
    float d = 0.0f;
    #pragma unroll
    for (int r = 0; r < 8; r++) d += fabsf(va[r] - vb[r]);
    #pragma unroll
    for (int off = 16; off > 0; off >>= 1)
        d += __shfl_xor_sync(0xffffffffu, d, off);
    if (lane == 0) wsum[w] = d;
    __syncthreads();

    if (tid == 0) {
        // transpose-pair symmetry -> factor 2; each LAP averaged over N
        const float scale = 2.0f / (float)NP;
        const int base = blockIdx.x * 8;
        #pragma unroll
        for (int i = 0; i < 8; i++)
            g_partial[base + i] = wsum[i] * scale;
        __threadfence();
        unsigned int old = atomicInc(&g_count, NBLK - 1);   // 1 -> wraps 0
        if (old == NBLK - 1) {           // last block: all partials visible
            float tot = 0.0f;
            #pragma unroll
            for (int i = 0; i < NCELL; i++) tot += __ldcg(&g_partial[i]);
            out[0] = tot;
        }
    }
}

extern "C" void kernel_launch(void* const* d_in, const int* in_sizes, int n_in,
                              void* d_out, int out_size) {
    const float* set1 = (const float*)d_in[0];
    const float* set2 = (const float*)d_in[1];
    float* out = (float*)d_out;

    hungarian_warpcell_kernel<<<NBLK, 256>>>(set1, set2, out);
}

// round 13
// speedup vs baseline: 1.2399x; 1.2399x over previous
#include <cuda_runtime.h>
#include <cuda_bf16.h>
#include <math.h>

// Problem constants (from reference): B=8, N=256, MAX_DIM=2, D=4, EPS=1e-8
#define NP 256
#define NBLK 8     // one block per batch
#define NCELL 16   // B * MAX_DIM partial sums

__device__ float g_partial[NCELL];
__device__ unsigned int g_count;   // static-init 0; atomicInc wraps back to 0

// 8 blocks x 256 threads. Block = one batch; four 64-thread groups:
//   group 0: set1/dim0   group 1: set2/dim0
//   group 2: set1/dim1   group 3: set2/dim1
// Each group sorts its 256-element projection with 4 elements/thread
// (e = 4t..4t+3; each warp spans 128 contiguous elements):
//   j in {1,2}  : in-register compare-exchange            (15 stages)
//   j in {4..64}: shfl_xor within warp (lane mask j>>2)   (20 stages)
//   j == 128    : single smem exchange (k=256 -> asc all-true)
// 8 warps/block = 2 per SMSP hides SHFL latency via warp interleaving.
// Sorted matching == optimal assignment for 1D L1 cost; the 2B LAPs come in
// transpose pairs with equal totals -> factor 2. Last finishing block sums the
// 16 per-cell partials in fixed index order (deterministic) into out[0].
__global__ __launch_bounds__(256)
void hungarian_batch_kernel(const float* __restrict__ set1,
                            const float* __restrict__ set2,
                            float* __restrict__ out) {
    __shared__ float sbuf[1024];    // j=128 exchange: 4 groups x 256
    __shared__ float dbuf[512];     // sorted set2 halves for the diff (no WAR)
    __shared__ float wsum[8];       // per-warp diff partials

    const int b = blockIdx.x;       // batch 0..7

    const int tid   = threadIdx.x;  // 0..255
    const int group = tid >> 6;     // 0..3
    const int t     = tid & 63;     // thread index within group
    const int lane  = tid & 31;
    const int dim   = group >> 1;   // 0,0,1,1
    const int isS2  = group & 1;    // 0 = set1, 1 = set2
    const float fdim = (float)dim;

    // --- projection: elements e = 4t .. 4t+3 ---
    float v[4];
    {
        const float4* src = (const float4*)(isS2 ? set2 : set1)
                          + (size_t)b * NP + 4 * t;
        #pragma unroll
        for (int r = 0; r < 4; r++) {
            float4 p = src[r];
            bool m;
            if (!isS2) {
                m = (p.z == fdim);
            } else {
                // jnp.argmax over (c2, c3): first max wins -> 1 iff c3 > c2
                m = (((p.w > p.z) ? 1 : 0) == dim);
            }
            v[r] = (m ? p.x : 0.0f) + sqrtf((m ? p.y : 0.0f) + 1e-8f) * 0.5f;
        }
    }

    // --- bitonic sort of 256 elements, 4 per thread ---
    #pragma unroll
    for (int k = 2; k <= NP; k <<= 1) {
        #pragma unroll
        for (int j = k >> 1; j > 0; j >>= 1) {
            if (j >= 128) {
                // single cross-warp stage: k=256 so asc is true for all e
                ((float4*)(sbuf + group * 256 + 4 * t))[0] =
                    make_float4(v[0], v[1], v[2], v[3]);
                __syncthreads();
                float4 o = ((float4*)(sbuf + group * 256 + ((4 * t) ^ 128)))[0];
                const bool takeMax = (t & 32) != 0;
                v[0] = takeMax ? fmaxf(v[0], o.x) : fminf(v[0], o.x);
                v[1] = takeMax ? fmaxf(v[1], o.y) : fminf(v[1], o.y);
                v[2] = takeMax ? fmaxf(v[2], o.z) : fminf(v[2], o.z);
                v[3] = takeMax ? fmaxf(v[3], o.w) : fminf(v[3], o.w);
            } else if (j >= 4) {
                const int lm = j >> 2;                     // partner lane mask
                const bool asc = (((4 * t) & k) == 0);     // same for r=0..3
                const bool takeMax = (((lane & lm) != 0) == asc);
                #pragma unroll
                for (int r = 0; r < 4; r++) {
                    float o = __shfl_xor_sync(0xffffffffu, v[r], lm);
                    v[r] = takeMax ? fmaxf(v[r], o) : fminf(v[r], o);
                }
            } else {
                // in-register: pairs (r, r^j)
                #pragma unroll
                for (int r = 0; r < 4; r++) {
                    const int p = r ^ j;
                    if (p > r) {
                        const bool asc = (((4 * t + r) & k) == 0);
                        float lo = fminf(v[r], v[p]);
                        float hi = fmaxf(v[r], v[p]);
                        v[r] = asc ? lo : hi;
                        v[p] = asc ? hi : lo;
                    }
                }
            }
        }
    }

    // --- L1 diff of sorted sequences (set2 groups publish to dbuf) ---
    if (isS2)       // dim0 -> dbuf[0:256), dim1 -> dbuf[256:512)
        ((float4*)(dbuf + dim * 256 + 4 * t))[0] =
            make_float4(v[0], v[1], v[2], v[3]);
    __syncthreads();
    float d = 0.0f;
    if (!isS2) {
        float4 o = ((float4*)(dbuf + dim * 256 + 4 * t))[0];
        d = fabsf(v[0] - o.x) + fabsf(v[1] - o.y)
          + fabsf(v[2] - o.z) + fabsf(v[3] - o.w);
    }
    #pragma unroll
    for (int off = 16; off > 0; off >>= 1)
        d += __shfl_xor_sync(0xffffffffu, d, off);
    if (lane == 0) wsum[tid >> 5] = d;   // warps 0,1 (dim0) and 4,5 (dim1)
    __syncthreads();

    // --- warp-0 epilogue: store partials, count arrivals, last block sums ---
    if (tid < 32) {
        unsigned int old = 0;
        if (lane == 0) {
            // transpose-pair symmetry -> factor 2; each LAP averaged over N
            const float scale = 2.0f / (float)NP;
            float2 pr = make_float2((wsum[0] + wsum[1]) * scale,   // dim 0
                                    (wsum[4] + wsum[5]) * scale);  // dim 1
            ((float2*)g_partial)[b] = pr;       // one 8B store
            __threadfence();                    // order store before count
            old = atomicInc(&g_count, NBLK - 1);   // 7 -> wraps 0
        }
        old = __shfl_sync(0xffffffffu, old, 0);
        if (old == NBLK - 1) {          // last block: all partials visible
            float tpart = (lane < NCELL) ? __ldcg(&g_partial[lane]) : 0.0f;
            #pragma unroll
            for (int off = 8; off > 0; off >>= 1)
                tpart += __shfl_xor_sync(0xffffffffu, tpart, off);
            if (lane == 0) out[0] = tpart;
        }
    }
}

extern "C" void kernel_launch(void* const* d_in, const int* in_sizes, int n_in,
                              void* d_out, int out_size) {
    const float* set1 = (const float*)d_in[0];
    const float* set2 = (const float*)d_in[1];
    float* out = (float*)d_out;

    hungarian_batch_kernel<<<NBLK, 256>>>(set1, set2, out);
}

// round 15
// speedup vs baseline: 1.3884x; 1.1198x over previous
#include <cuda_runtime.h>
#include <cuda_bf16.h>
#include <math.h>
#include <cstdint>

// Problem constants (from reference): B=8, N=256, MAX_DIM=2, D=4, EPS=1e-8
#define NP 256
#define NBLK 8     // one block per batch; all 8 blocks form one cluster
#define NCELL 16   // B * MAX_DIM partial sums

// 8-block CGA x 256 threads. Block = one batch; four 64-thread groups:
//   group 0: set1/dim0   group 1: set2/dim0
//   group 2: set1/dim1   group 3: set2/dim1
// Each group sorts its 256-element projection with 4 elements/thread
// (e = 4t..4t+3; each warp spans 128 contiguous elements):
//   j in {1,2}  : in-register compare-exchange            (15 stages)
//   j in {4..64}: shfl_xor within warp (lane mask j>>2)   (20 stages)
//   j == 128    : single smem exchange (k=256 -> asc all-true)
// 8 warps/block = 2 per SMSP hides SHFL latency via warp interleaving.
// Epilogue: every block DSMEM-stores its float2 partial into rank 0's smem,
// one cluster barrier orders the stores, and rank 0 reduces from LOCAL smem.
// No global scratch, no atomics, no threadfence -> shorter tail, fully
// deterministic (fixed-order reduction).
// Sorted matching == optimal assignment for 1D L1 cost; the 2B LAPs come in
// transpose pairs with equal totals -> factor 2.
__global__ __launch_bounds__(256) __cluster_dims__(NBLK, 1, 1)
void hungarian_cluster_kernel(const float* __restrict__ set1,
                              const float* __restrict__ set2,
                              float* __restrict__ out) {
    __shared__ float sbuf[1024];                  // j=128 exchange: 4 x 256
    __shared__ float dbuf[512];                   // sorted set2 halves (no WAR)
    __shared__ float wsum[8];                     // per-warp diff partials
    __shared__ __align__(16) float partials[NCELL];  // rank 0 aggregation

    const int b = blockIdx.x;       // batch 0..7 == cluster rank

    const int tid   = threadIdx.x;  // 0..255
    const int group = tid >> 6;     // 0..3
    const int t     = tid & 63;     // thread index within group
    const int lane  = tid & 31;
    const int dim   = group >> 1;   // 0,0,1,1
    const int isS2  = group & 1;    // 0 = set1, 1 = set2
    const float fdim = (float)dim;

    // --- projection: elements e = 4t .. 4t+3 ---
    float v[4];
    {
        const float4* src = (const float4*)(isS2 ? set2 : set1)
                          + (size_t)b * NP + 4 * t;
        #pragma unroll
        for (int r = 0; r < 4; r++) {
            float4 p = src[r];
            bool m;
            if (!isS2) {
                m = (p.z == fdim);
            } else {
                // jnp.argmax over (c2, c3): first max wins -> 1 iff c3 > c2
                m = (((p.w > p.z) ? 1 : 0) == dim);
            }
            v[r] = (m ? p.x : 0.0f) + sqrtf((m ? p.y : 0.0f) + 1e-8f) * 0.5f;
        }
    }

    // --- bitonic sort of 256 elements, 4 per thread ---
    #pragma unroll
    for (int k = 2; k <= NP; k <<= 1) {
        #pragma unroll
        for (int j = k >> 1; j > 0; j >>= 1) {
            if (j >= 128) {
                // single cross-warp stage: k=256 so asc is true for all e
                ((float4*)(sbuf + group * 256 + 4 * t))[0] =
                    make_float4(v[0], v[1], v[2], v[3]);
                __syncthreads();
                float4 o = ((float4*)(sbuf + group * 256 + ((4 * t) ^ 128)))[0];
                const bool takeMax = (t & 32) != 0;
                v[0] = takeMax ? fmaxf(v[0], o.x) : fminf(v[0], o.x);
                v[1] = takeMax ? fmaxf(v[1], o.y) : fminf(v[1], o.y);
                v[2] = takeMax ? fmaxf(v[2], o.z) : fminf(v[2], o.z);
                v[3] = takeMax ? fmaxf(v[3], o.w) : fminf(v[3], o.w);
            } else if (j >= 4) {
                const int lm = j >> 2;                     // partner lane mask
                const bool asc = (((4 * t) & k) == 0);     // same for r=0..3
                const bool takeMax = (((lane & lm) != 0) == asc);
                #pragma unroll
                for (int r = 0; r < 4; r++) {
                    float o = __shfl_xor_sync(0xffffffffu, v[r], lm);
                    v[r] = takeMax ? fmaxf(v[r], o) : fminf(v[r], o);
                }
            } else {
                // in-register: pairs (r, r^j)
                #pragma unroll
                for (int r = 0; r < 4; r++) {
                    const int p = r ^ j;
                    if (p > r) {
                        const bool asc = (((4 * t + r) & k) == 0);
                        float lo = fminf(v[r], v[p]);
                        float hi = fmaxf(v[r], v[p]);
                        v[r] = asc ? lo : hi;
                        v[p] = asc ? hi : lo;
                    }
                }
            }
        }
    }

    // --- L1 diff of sorted sequences (set2 groups publish to dbuf) ---
    if (isS2)       // dim0 -> dbuf[0:256), dim1 -> dbuf[256:512)
        ((float4*)(dbuf + dim * 256 + 4 * t))[0] =
            make_float4(v[0], v[1], v[2], v[3]);
    __syncthreads();
    float d = 0.0f;
    if (!isS2) {
        float4 o = ((float4*)(dbuf + dim * 256 + 4 * t))[0];
        d = fabsf(v[0] - o.x) + fabsf(v[1] - o.y)
          + fabsf(v[2] - o.z) + fabsf(v[3] - o.w);
    }
    #pragma unroll
    for (int off = 16; off > 0; off >>= 1)
        d += __shfl_xor_sync(0xffffffffu, d, off);
    if (lane == 0) wsum[tid >> 5] = d;   // warps 0,1 (dim0) and 4,5 (dim1)
    __syncthreads();

    // --- DSMEM epilogue: push this block's 2 partials into rank 0's smem ---
    if (tid == 0) {
        // transpose-pair symmetry -> factor 2; each LAP averaged over N
        const float scale = 2.0f / (float)NP;
        float p0 = (wsum[0] + wsum[1]) * scale;   // dim 0
        float p1 = (wsum[4] + wsum[5]) * scale;   // dim 1
        unsigned long long pk =
            (unsigned long long)__float_as_uint(p0)
          | ((unsigned long long)__float_as_uint(p1) << 32);
        uint32_t laddr = (uint32_t)__cvta_generic_to_shared(&partials[2 * b]);
        uint32_t raddr;
        asm volatile("mapa.shared::cluster.u32 %0, %1, 0;"
                     : "=r"(raddr) : "r"(laddr));
        asm volatile("st.shared::cluster.b64 [%0], %1;"
                     :: "r"(raddr), "l"(pk) : "memory");
    }
    // cluster barrier: arrive has release, wait has acquire -> DSMEM stores
    // above are visible to rank 0's reads below.
    asm volatile("barrier.cluster.arrive.aligned;" ::: "memory");
    asm volatile("barrier.cluster.wait.aligned;" ::: "memory");

    uint32_t rank;
    asm("mov.u32 %0, %%cluster_ctarank;" : "=r"(rank));
    if (rank == 0 && tid < 32) {
        float tp = (lane < NCELL) ? partials[lane] : 0.0f;
        #pragma unroll
        for (int off = 8; off > 0; off >>= 1)
            tp += __shfl_xor_sync(0xffffffffu, tp, off);
        if (lane == 0) out[0] = tp;
    }
}

extern "C" void kernel_launch(void* const* d_in, const int* in_sizes, int n_in,
                              void* d_out, int out_size) {
    const float* set1 = (const float*)d_in[0];
    const float* set2 = (const float*)d_in[1];
    float* out = (float*)d_out;

    hungarian_cluster_kernel<<<NBLK, 256>>>(set1, set2, out);
}